// round 15
// baseline (speedup 1.0000x reference)
#include <cuda_runtime.h>
#include <cuda_bf16.h>
#include <cstdint>

#define NB 4
#define NS 4096
#define QT 64               // q rows per CTA (attn)
#define KT 64               // keys per tile (attn)
#define NIT (NS/KT)         // 64 tiles

// Projected tensors, module-static scratch.
__device__ uint32_t      g_qb[(size_t)NB*NS*32];   // packed bf16 pairs, perm'd
__device__ uint32_t      g_kb[(size_t)NB*NS*32];
__device__ __nv_bfloat16 g_vh[(size_t)NB*64*NS];   // bf16 V [b][d][s], s perm'd
__device__ float         g_svp[256*64];            // per-V-block column-sum partials
__device__ float         g_sv[NB*64];              // exact fp32 column sums of V

__device__ __forceinline__ uint32_t smem_to_u32(const void* p) {
    uint32_t a;
    asm("{ .reg .u64 t; cvta.to.shared.u64 t, %1; cvt.u32.u64 %0, t; }" : "=r"(a) : "l"(p));
    return a;
}
__device__ __forceinline__ void cpa16(uint32_t dst, const void* src) {
    asm volatile("cp.async.cg.shared.global [%0], [%1], 16;" :: "r"(dst), "l"(src) : "memory");
}
#define CP_COMMIT() asm volatile("cp.async.commit_group;" ::: "memory")
#define CP_WAIT0()  asm volatile("cp.async.wait_group 0;" ::: "memory")

__device__ __forceinline__ void mma_bf16(float c[4], const uint32_t a[4],
                                         uint32_t b0, uint32_t b1) {
    asm volatile("mma.sync.aligned.m16n8k16.row.col.f32.bf16.bf16.f32 "
        "{%0,%1,%2,%3}, {%4,%5,%6,%7}, {%8,%9}, {%0,%1,%2,%3};"
        : "+f"(c[0]), "+f"(c[1]), "+f"(c[2]), "+f"(c[3])
        : "r"(a[0]), "r"(a[1]), "r"(a[2]), "r"(a[3]), "r"(b0), "r"(b1));
}
__device__ __forceinline__ uint32_t pack2(float lo, float hi) {
    __nv_bfloat162 h = __float22bfloat162_rn(make_float2(lo, hi));
    return *reinterpret_cast<uint32_t*>(&h);
}
__device__ __forceinline__ uint32_t pack2f(float2 v) { return pack2(v.x, v.y); }
// fragment word permutation within 8-word groups
__device__ __forceinline__ int permw(int w) {
    return (w & ~7) | (((w & 3) << 1) | ((w >> 2) & 1));
}

// ===========================================================================
// Projection via tensor cores (unchanged from R14). Grid 512 x 128 threads.
// ===========================================================================
__global__ __launch_bounds__(128) void proj_kernel(
    const float* __restrict__ q, const float* __restrict__ k, const float* __restrict__ v,
    const float* __restrict__ Wq, const float* __restrict__ bq,
    const float* __restrict__ Wk, const float* __restrict__ bk,
    const float* __restrict__ Wv, const float* __restrict__ bv,
    const float* __restrict__ qw, const float* __restrict__ kw)
{
    __shared__ __align__(16) char smem[36864];
    uint32_t* sWbh = (uint32_t*)smem;
    uint32_t* sWbl = (uint32_t*)(smem + 8704);
    float*    sCo  = (float*)(smem + 17408);
    uint32_t* sQ   = (uint32_t*)(smem + 17920);
    float*    sVt  = (float*)(smem + 17920);
    float*    sPart= (float*)(smem + 36352);

    const int blk = blockIdx.x;
    const int mat = (blk < 128) ? 0 : (blk < 256) ? 1 : 2;
    const int tid = threadIdx.x;
    const int wr  = tid >> 5;
    const int lane = tid & 31;
    const int g   = lane >> 2;
    const int tg  = lane & 3;

    const float* src  = (mat == 0) ? q  : (mat == 1) ? k  : v;
    const float* W    = (mat == 0) ? Wq : (mat == 1) ? Wk : Wv;
    const float* bias = (mat == 0) ? bq : (mat == 1) ? bk : bv;
    const float* wvp  = (mat == 0) ? qw : kw;

    const int rowbase = (mat == 2) ? (blk - 256) * 64 : (blk & 127) * 128;

    for (int wdx = tid; wdx < 2048; wdx += 128) {
        const int j = wdx >> 5, p = wdx & 31;
        float2 w2 = *(const float2*)(W + j*64 + 2*p);
        const int pos = j*34 + ((p & 24) | (((p & 3) << 1) | ((p >> 2) & 1)));
        if (mat < 2) {
            sWbh[pos] = pack2f(w2);
        } else {
            __nv_bfloat16 h0 = __float2bfloat16(w2.x), h1 = __float2bfloat16(w2.y);
            sWbh[pos] = ((uint32_t)__bfloat16_as_ushort(h1) << 16) |
                        (uint32_t)__bfloat16_as_ushort(h0);
            sWbl[pos] = pack2(w2.x - __bfloat162float(h0), w2.y - __bfloat162float(h1));
        }
    }
    if (tid < 64) {
        if (mat < 2) {
            float m = wvp[tid] * (1.0f/64.0f);
            sCo[tid] = m; sCo[64 + tid] = bias[tid] * m;
        } else {
            sCo[tid] = bias[tid];
        }
    }

    if (mat < 2) {
        const int rb = wr * 32;
        uint32_t A[2][4][4];
        #pragma unroll
        for (int rt = 0; rt < 2; rt++) {
            const float* xg = src + (size_t)(rowbase + rb + rt*16 + g)*64 + 2*tg;
            const float* xh = xg + 8*64;
            #pragma unroll
            for (int ks = 0; ks < 4; ks++) {
                float2 x0 = *(const float2*)(xg + ks*16);
                float2 x1 = *(const float2*)(xh + ks*16);
                float2 x2 = *(const float2*)(xg + ks*16 + 8);
                float2 x3 = *(const float2*)(xh + ks*16 + 8);
                A[rt][ks][0] = pack2f(x0); A[rt][ks][1] = pack2f(x1);
                A[rt][ks][2] = pack2f(x2); A[rt][ks][3] = pack2f(x3);
            }
        }
        __syncthreads();
        #pragma unroll
        for (int rt = 0; rt < 2; rt++) {
            const int r0 = rb + rt*16 + g;
            #pragma unroll
            for (int j8 = 0; j8 < 8; j8++) {
                const uint32_t* wrow = sWbh + (j8*8 + g)*34 + 2*tg;
                float C[4] = {0.f, 0.f, 0.f, 0.f};
                #pragma unroll
                for (int ks = 0; ks < 4; ks++) {
                    uint2 bf = *(const uint2*)(wrow + ks*8);
                    mma_bf16(C, A[rt][ks], bf.x, bf.y);
                }
                const int c = j8*8 + 2*tg;
                const float m0 = sCo[c], m1 = sCo[c+1];
                const float a0 = sCo[64+c], a1 = sCo[64+c+1];
                const int wp = permw(j8*4 + tg);
                sQ[(r0    )*36 + wp] = pack2(fmaf(C[0],m0,a0), fmaf(C[1],m1,a1));
                sQ[(r0 + 8)*36 + wp] = pack2(fmaf(C[2],m0,a0), fmaf(C[3],m1,a1));
            }
        }
        __syncthreads();
        uint32_t* dst = ((mat == 0) ? g_qb : g_kb) + (size_t)rowbase * 32;
        #pragma unroll
        for (int i = 0; i < 8; i++) {
            const int c = tid + i*128;
            const int row = c >> 3, qq = c & 7;
            uint4 u = *(const uint4*)(sQ + row*36 + 4*qq);
            *((uint4*)dst + (size_t)row*8 + qq) = u;
        }
    } else {
        const int r0 = wr*16 + g;
        uint32_t Ah[4][4], Al[4][4];
        {
            const float* xg = src + (size_t)(rowbase + r0)*64 + 2*tg;
            const float* xh = xg + 8*64;
            #pragma unroll
            for (int ks = 0; ks < 4; ks++) {
                float2 xs[4];
                xs[0] = *(const float2*)(xg + ks*16);
                xs[1] = *(const float2*)(xh + ks*16);
                xs[2] = *(const float2*)(xg + ks*16 + 8);
                xs[3] = *(const float2*)(xh + ks*16 + 8);
                #pragma unroll
                for (int e = 0; e < 4; e++) {
                    __nv_bfloat16 h0 = __float2bfloat16(xs[e].x);
                    __nv_bfloat16 h1 = __float2bfloat16(xs[e].y);
                    Ah[ks][e] = ((uint32_t)__bfloat16_as_ushort(h1) << 16) |
                                (uint32_t)__bfloat16_as_ushort(h0);
                    Al[ks][e] = pack2(xs[e].x - __bfloat162float(h0),
                                      xs[e].y - __bfloat162float(h1));
                }
            }
        }
        __syncthreads();
        #pragma unroll
        for (int j8 = 0; j8 < 8; j8++) {
            const uint32_t* wrh = sWbh + (j8*8 + g)*34 + 2*tg;
            const uint32_t* wrl = sWbl + (j8*8 + g)*34 + 2*tg;
            float C[4] = {0.f, 0.f, 0.f, 0.f};
            #pragma unroll
            for (int ks = 0; ks < 4; ks++) {
                uint2 bh = *(const uint2*)(wrh + ks*8);
                uint2 bl = *(const uint2*)(wrl + ks*8);
                mma_bf16(C, Ah[ks], bh.x, bh.y);
                mma_bf16(C, Al[ks], bh.x, bh.y);
                mma_bf16(C, Ah[ks], bl.x, bl.y);
            }
            const int d = j8*8 + 2*tg;
            const float a0 = sCo[d], a1 = sCo[d+1];
            *(float2*)(sVt + (r0    )*66 + d) = make_float2(C[0]+a0, C[1]+a1);
            *(float2*)(sVt + (r0 + 8)*66 + d) = make_float2(C[2]+a0, C[3]+a1);
        }
        __syncthreads();
        {
            const int d  = tid >> 1;
            const int sh = tid & 1;
            const int b  = rowbase >> 12, sb = rowbase & (NS-1);
            uint32_t* dst = (uint32_t*)g_vh + (((size_t)(b*64 + d))*NS + sb)/2;
            #pragma unroll
            for (int j = 0; j < 2; j++) {
                const int sblk = sh*2 + j;
                float x[16];
                #pragma unroll
                for (int i = 0; i < 16; i++) x[i] = sVt[(sblk*16 + i)*66 + d];
                uint4* o4 = (uint4*)(dst + sblk*8);
                o4[0] = make_uint4(pack2(x[0],x[1]), pack2(x[ 8],x[ 9]),
                                   pack2(x[2],x[3]), pack2(x[10],x[11]));
                o4[1] = make_uint4(pack2(x[4],x[5]), pack2(x[12],x[13]),
                                   pack2(x[6],x[7]), pack2(x[14],x[15]));
            }
        }
        {
            const int d    = tid & 63;
            const int half = tid >> 6;
            float acc = 0.0f;
            #pragma unroll
            for (int i = 0; i < 32; i++)
                acc += sVt[(half*32 + i)*66 + d];
            sPart[tid] = acc;
        }
        __syncthreads();
        if (tid < 64)
            g_svp[(size_t)(blk - 256)*64 + tid] = sPart[tid] + sPart[tid + 64];
    }
}

// ===========================================================================
// Reduce V column-sum partials (deterministic fixed order).
// ===========================================================================
__global__ __launch_bounds__(64) void sumv_kernel()
{
    const int b = blockIdx.x;
    const int d = threadIdx.x;
    float acc = 0.0f;
    #pragma unroll 8
    for (int j = 0; j < 64; j++)
        acc += g_svp[(size_t)(b*64 + j)*64 + d];
    g_sv[b*64 + d] = acc;
}

// ===========================================================================
// Flash attention, bf16 mma, e = exp(s)-1 decomposition.
// QT=64, KT=64; 256 threads = 2 row-groups(32 rows) x 4 key-quarters(16 keys)
// -> grid 256 CTAs, 2 CTAs/SM, 4 warp streams per SMSP.
//   O = (SumV + Sum e_i v_i) / (4096 + Sum e_i)
// ===========================================================================
#define PQK 40
#define PV  40
#define KWORDS (KT*PQK)        // 2560
#define VWORDS (64*PV)         // 2560
#define STG (KWORDS + VWORDS)  // 5120 words = 20480 B per stage

#define POLY_E(sv) ((sv) * fmaf((sv), fmaf((sv), 0.16666667f, 0.5f), 1.0f))

__global__ __launch_bounds__(256, 2) void attn_kernel(float* __restrict__ out)
{
    __shared__ __align__(16) uint32_t buf[2*STG];   // 40960 B
    float* buff = (float*)buf;

    const int tid  = threadIdx.x;
    const int lane = tid & 31;
    const int w    = tid >> 5;
    const int wr   = w & 1;              // row group (32 q rows)
    const int hf   = w >> 1;             // key quarter (16 keys of 64)
    const int g    = lane >> 2;
    const int tg   = lane & 3;
    const int b    = blockIdx.y;
    const int qbase = blockIdx.x * QT;
    const uint32_t sbase = smem_to_u32(buf);

    // ---------------- Q phase: 64 rows, 4 threads/row (2 uint4 each) -------
    {
        const int qr = tid >> 2;
        const int q4 = tid & 3;
        const uint4* qg = (const uint4*)g_qb + ((size_t)(b*NS + qbase + qr)) * 8;
        *(uint4*)(buf + qr*PQK + (q4*2    )*4) = qg[q4*2];
        *(uint4*)(buf + qr*PQK + (q4*2 + 1)*4) = qg[q4*2 + 1];
    }
    __syncthreads();

    uint32_t qa[2][4][4];
    #pragma unroll
    for (int rt = 0; rt < 2; rt++) {
        const int r0 = wr*32 + rt*16 + g;
        #pragma unroll
        for (int kp = 0; kp < 4; kp++) {
            uint2 u0 = *(const uint2*)(buf + (r0  )*PQK + kp*8 + 2*tg);
            uint2 u1 = *(const uint2*)(buf + (r0+8)*PQK + kp*8 + 2*tg);
            qa[rt][kp][0] = u0.x; qa[rt][kp][1] = u1.x;
            qa[rt][kp][2] = u0.y; qa[rt][kp][3] = u1.y;
        }
    }
    __syncthreads();

    // ---------------- cp.async staging: 4 x 16B per thread per tile --------
    const int kr0  = tid >> 3;
    const int slot = tid & 7;
    const uint4* kgm  = (const uint4*)g_kb + (size_t)b*NS*8;
    const uint4* vhg0 = (const uint4*)g_vh + ((size_t)(b*64 + kr0     ))*(NS/8);
    const uint4* vhg1 = (const uint4*)g_vh + ((size_t)(b*64 + kr0 + 32))*(NS/8);
    const uint32_t kst0 = sbase + ((kr0     )*PQK + slot*4)*4;
    const uint32_t kst1 = sbase + ((kr0 + 32)*PQK + slot*4)*4;
    const uint32_t vst0 = sbase + (KWORDS + (kr0     )*PV + slot*4)*4;
    const uint32_t vst1 = sbase + (KWORDS + (kr0 + 32)*PV + slot*4)*4;

    {
        cpa16(kst0, kgm + (size_t)(kr0     )*8 + slot);
        cpa16(kst1, kgm + (size_t)(kr0 + 32)*8 + slot);
        cpa16(vst0, vhg0 + slot);
        cpa16(vst1, vhg1 + slot);
        CP_COMMIT();
    }

    float o[2][8][4];
    #pragma unroll
    for (int rt = 0; rt < 2; rt++)
        #pragma unroll
        for (int n = 0; n < 8; n++)
            #pragma unroll
            for (int e = 0; e < 4; e++) o[rt][n][e] = 0.0f;
    float lsum[2][2] = {{0.f,0.f},{0.f,0.f}};

    #pragma unroll 1
    for (int kt = 0; kt < NIT; kt++) {
        const int cur = kt & 1;
        CP_WAIT0();
        __syncthreads();
        if (kt + 1 < NIT) {
            const uint32_t off = (cur^1) * (STG*4);
            cpa16(kst0 + off, kgm + (size_t)((kt+1)*KT + kr0     )*8 + slot);
            cpa16(kst1 + off, kgm + (size_t)((kt+1)*KT + kr0 + 32)*8 + slot);
            cpa16(vst0 + off, vhg0 + (kt+1)*8 + slot);
            cpa16(vst1 + off, vhg1 + (kt+1)*8 + slot);
            CP_COMMIT();
        }
        const uint32_t* sK = buf + cur*STG;
        const uint32_t* sV = sK + KWORDS;

        // ---- MMA1: S(32x16) = Q @ K_quarter^T (2 n-tiles of 8 keys) ----
        float s[2][2][4];
        #pragma unroll
        for (int n = 0; n < 2; n++) {
            const uint32_t* krow = sK + (hf*16 + n*8 + g)*PQK + 2*tg;
            uint2 k0 = *(const uint2*)(krow     );
            uint2 k1 = *(const uint2*)(krow +  8);
            uint2 k2 = *(const uint2*)(krow + 16);
            uint2 k3 = *(const uint2*)(krow + 24);
            float sa[2][4] = {{0.f,0.f,0.f,0.f},{0.f,0.f,0.f,0.f}};
            float sb[2][4] = {{0.f,0.f,0.f,0.f},{0.f,0.f,0.f,0.f}};
            mma_bf16(sa[0], qa[0][0], k0.x, k0.y);
            mma_bf16(sa[1], qa[1][0], k0.x, k0.y);
            mma_bf16(sb[0], qa[0][1], k1.x, k1.y);
            mma_bf16(sb[1], qa[1][1], k1.x, k1.y);
            mma_bf16(sa[0], qa[0][2], k2.x, k2.y);
            mma_bf16(sa[1], qa[1][2], k2.x, k2.y);
            mma_bf16(sb[0], qa[0][3], k3.x, k3.y);
            mma_bf16(sb[1], qa[1][3], k3.x, k3.y);
            #pragma unroll
            for (int rt = 0; rt < 2; rt++)
                #pragma unroll
                for (int e = 0; e < 4; e++) s[rt][n][e] = sa[rt][e] + sb[rt][e];
        }

        // ---- e = poly(s); pack one k16 A-frag (16 keys) per rt ----
        uint32_t ea[2][4];
        #pragma unroll
        for (int rt = 0; rt < 2; rt++) {
            float e00 = POLY_E(s[rt][0][0]), e01 = POLY_E(s[rt][0][1]);
            float e02 = POLY_E(s[rt][0][2]), e03 = POLY_E(s[rt][0][3]);
            float e10 = POLY_E(s[rt][1][0]), e11 = POLY_E(s[rt][1][1]);
            float e12 = POLY_E(s[rt][1][2]), e13 = POLY_E(s[rt][1][3]);
            lsum[rt][0] += (e00 + e01) + (e10 + e11);
            lsum[rt][1] += (e02 + e03) + (e12 + e13);
            ea[rt][0] = pack2(e00, e01);   // row g,   keys lo (n-tile 0)
            ea[rt][1] = pack2(e02, e03);   // row g+8, keys lo
            ea[rt][2] = pack2(e10, e11);   // row g,   keys hi (n-tile 1)
            ea[rt][3] = pack2(e12, e13);   // row g+8, keys hi
        }

        // ---- MMA2: O(32x64) += E(32x16) @ V_quarter(16x64) ----
        #pragma unroll
        for (int n = 0; n < 8; n++) {
            const uint32_t* vrow = sV + (n*8 + g)*PV + hf*8 + 2*tg;
            uint2 bv2 = *(const uint2*)(vrow);
            mma_bf16(o[0][n], ea[0], bv2.x, bv2.y);
            mma_bf16(o[1][n], ea[1], bv2.x, bv2.y);
        }
    }
    __syncthreads();

    // ---------------- epilogue: pairwise tree over 4 key-quarters ----------
    #pragma unroll
    for (int rt = 0; rt < 2; rt++)
        #pragma unroll
        for (int h = 0; h < 2; h++) {
            lsum[rt][h] += __shfl_xor_sync(0xffffffffu, lsum[rt][h], 1);
            lsum[rt][h] += __shfl_xor_sync(0xffffffffu, lsum[rt][h], 2);
        }

    float* bufA = buff;                  // 64x64 fp32
    float* bufB = buff + 4096;
    float* lsA  = buff + 8192;           // 64 floats
    float* lsB  = buff + 8256;

    // step 1: hf==1 -> bufA, hf==3 -> bufB
    if (hf == 1 || hf == 3) {
        float* ob = (hf == 1) ? bufA : bufB;
        float* lb = (hf == 1) ? lsA  : lsB;
        #pragma unroll
        for (int rt = 0; rt < 2; rt++) {
            const int r0 = wr*32 + rt*16 + g;
            #pragma unroll
            for (int n = 0; n < 8; n++) {
                *(float2*)(ob + (size_t)r0*64 + n*8 + 2*tg)     = make_float2(o[rt][n][0], o[rt][n][1]);
                *(float2*)(ob + (size_t)(r0+8)*64 + n*8 + 2*tg) = make_float2(o[rt][n][2], o[rt][n][3]);
            }
            if (tg == 0) {
                lb[r0]     = lsum[rt][0];
                lb[r0 + 8] = lsum[rt][1];
            }
        }
    }
    __syncthreads();
    // step 2: hf==0 absorbs A (regs); hf==2 absorbs B then writes combined B
    if (hf == 0 || hf == 2) {
        float* ob = (hf == 0) ? bufA : bufB;
        float* lb = (hf == 0) ? lsA  : lsB;
        #pragma unroll
        for (int rt = 0; rt < 2; rt++) {
            const int r0 = wr*32 + rt*16 + g;
            #pragma unroll
            for (int n = 0; n < 8; n++) {
                float2 p0 = *(float2*)(ob + (size_t)r0*64 + n*8 + 2*tg);
                float2 p1 = *(float2*)(ob + (size_t)(r0+8)*64 + n*8 + 2*tg);
                o[rt][n][0] += p0.x; o[rt][n][1] += p0.y;
                o[rt][n][2] += p1.x; o[rt][n][3] += p1.y;
            }
            lsum[rt][0] += lb[r0];
            lsum[rt][1] += lb[r0 + 8];
        }
    }
    __syncthreads();
    if (hf == 2) {
        #pragma unroll
        for (int rt = 0; rt < 2; rt++) {
            const int r0 = wr*32 + rt*16 + g;
            #pragma unroll
            for (int n = 0; n < 8; n++) {
                *(float2*)(bufB + (size_t)r0*64 + n*8 + 2*tg)     = make_float2(o[rt][n][0], o[rt][n][1]);
                *(float2*)(bufB + (size_t)(r0+8)*64 + n*8 + 2*tg) = make_float2(o[rt][n][2], o[rt][n][3]);
            }
            if (tg == 0) {
                lsB[r0]     = lsum[rt][0];
                lsB[r0 + 8] = lsum[rt][1];
            }
        }
    }
    __syncthreads();
    // step 3: hf==0 adds combined B, normalizes, stores
    if (hf == 0) {
        float2 sv2[8];
        #pragma unroll
        for (int n = 0; n < 8; n++)
            sv2[n] = *(const float2*)(g_sv + b*64 + n*8 + 2*tg);
        #pragma unroll
        for (int rt = 0; rt < 2; rt++) {
            const int r0 = wr*32 + rt*16 + g;
            const float l0 = 1.0f / (4096.0f + lsum[rt][0] + lsB[r0]);
            const float l1 = 1.0f / (4096.0f + lsum[rt][1] + lsB[r0 + 8]);
            #pragma unroll
            for (int n = 0; n < 8; n++) {
                float2 e0 = *(float2*)(bufB + (size_t)r0*64 + n*8 + 2*tg);
                float2 e1 = *(float2*)(bufB + (size_t)(r0+8)*64 + n*8 + 2*tg);
                float2 v0 = make_float2((sv2[n].x + o[rt][n][0] + e0.x)*l0,
                                        (sv2[n].y + o[rt][n][1] + e0.y)*l0);
                float2 v1 = make_float2((sv2[n].x + o[rt][n][2] + e1.x)*l1,
                                        (sv2[n].y + o[rt][n][3] + e1.y)*l1);
                *(float2*)(out + ((size_t)(b*NS + qbase + r0    ))*64 + n*8 + 2*tg) = v0;
                *(float2*)(out + ((size_t)(b*NS + qbase + r0 + 8))*64 + n*8 + 2*tg) = v1;
            }
        }
    }
}

// ---------------------------------------------------------------------------
// Inputs: 0:q 1:k 2:v 3:attn_mask 4:Wq 5:bq 6:Wk 7:bk 8:Wv 9:bv 10:qw 11:kw
// attn_mask is a broadcast scalar added to all scores -> softmax-invariant.
// ---------------------------------------------------------------------------
extern "C" void kernel_launch(void* const* d_in, const int* in_sizes, int n_in,
                              void* d_out, int out_size)
{
    (void)in_sizes; (void)n_in; (void)out_size;
    proj_kernel<<<512, 128>>>(
        (const float*)d_in[0], (const float*)d_in[1], (const float*)d_in[2],
        (const float*)d_in[4], (const float*)d_in[5],
        (const float*)d_in[6], (const float*)d_in[7],
        (const float*)d_in[8], (const float*)d_in[9],
        (const float*)d_in[10], (const float*)d_in[11]);
    sumv_kernel<<<NB, 64>>>();
    attn_kernel<<<dim3(NS/QT, NB), 256>>>((float*)d_out);
}

// round 16
// speedup vs baseline: 1.0126x; 1.0126x over previous
#include <cuda_runtime.h>
#include <cuda_bf16.h>
#include <cstdint>

#define NB 4
#define NS 4096
#define QT 128              // q rows per CTA (attn)
#define KT 64               // keys per tile (attn)
#define NIT (NS/KT)         // 64 tiles total
#define HT  (NIT/2)         // 32 tiles per kv-half

// Projected tensors, module-static scratch.
__device__ uint32_t      g_qb[(size_t)NB*NS*32];   // packed bf16 pairs, perm'd
__device__ uint32_t      g_kb[(size_t)NB*NS*32];
__device__ __nv_bfloat16 g_vh[(size_t)NB*64*NS];   // bf16 V [b][d][s], s perm'd
__device__ float         g_svp[256*64];            // per-V-block column-sum partials
__device__ float         g_sv[NB*64];              // exact fp32 column sums of V
// split-K partials: [z][b][row][d] and [z][b][row]
__device__ float         g_op[(size_t)2*NB*NS*64];
__device__ float         g_lp[2*NB*NS];

__device__ __forceinline__ uint32_t smem_to_u32(const void* p) {
    uint32_t a;
    asm("{ .reg .u64 t; cvta.to.shared.u64 t, %1; cvt.u32.u64 %0, t; }" : "=r"(a) : "l"(p));
    return a;
}
__device__ __forceinline__ void cpa16(uint32_t dst, const void* src) {
    asm volatile("cp.async.cg.shared.global [%0], [%1], 16;" :: "r"(dst), "l"(src) : "memory");
}
#define CP_COMMIT() asm volatile("cp.async.commit_group;" ::: "memory")
#define CP_WAIT0()  asm volatile("cp.async.wait_group 0;" ::: "memory")

__device__ __forceinline__ void mma_bf16(float c[4], const uint32_t a[4],
                                         uint32_t b0, uint32_t b1) {
    asm volatile("mma.sync.aligned.m16n8k16.row.col.f32.bf16.bf16.f32 "
        "{%0,%1,%2,%3}, {%4,%5,%6,%7}, {%8,%9}, {%0,%1,%2,%3};"
        : "+f"(c[0]), "+f"(c[1]), "+f"(c[2]), "+f"(c[3])
        : "r"(a[0]), "r"(a[1]), "r"(a[2]), "r"(a[3]), "r"(b0), "r"(b1));
}
__device__ __forceinline__ uint32_t pack2(float lo, float hi) {
    __nv_bfloat162 h = __float22bfloat162_rn(make_float2(lo, hi));
    return *reinterpret_cast<uint32_t*>(&h);
}
__device__ __forceinline__ uint32_t pack2f(float2 v) { return pack2(v.x, v.y); }
// fragment word permutation within 8-word groups
__device__ __forceinline__ int permw(int w) {
    return (w & ~7) | (((w & 3) << 1) | ((w >> 2) & 1));
}

// ===========================================================================
// Projection via tensor cores (unchanged from R14). Grid 512 x 128 threads.
// ===========================================================================
__global__ __launch_bounds__(128) void proj_kernel(
    const float* __restrict__ q, const float* __restrict__ k, const float* __restrict__ v,
    const float* __restrict__ Wq, const float* __restrict__ bq,
    const float* __restrict__ Wk, const float* __restrict__ bk,
    const float* __restrict__ Wv, const float* __restrict__ bv,
    const float* __restrict__ qw, const float* __restrict__ kw)
{
    __shared__ __align__(16) char smem[36864];
    uint32_t* sWbh = (uint32_t*)smem;
    uint32_t* sWbl = (uint32_t*)(smem + 8704);
    float*    sCo  = (float*)(smem + 17408);
    uint32_t* sQ   = (uint32_t*)(smem + 17920);
    float*    sVt  = (float*)(smem + 17920);
    float*    sPart= (float*)(smem + 36352);

    const int blk = blockIdx.x;
    const int mat = (blk < 128) ? 0 : (blk < 256) ? 1 : 2;
    const int tid = threadIdx.x;
    const int wr  = tid >> 5;
    const int lane = tid & 31;
    const int g   = lane >> 2;
    const int tg  = lane & 3;

    const float* src  = (mat == 0) ? q  : (mat == 1) ? k  : v;
    const float* W    = (mat == 0) ? Wq : (mat == 1) ? Wk : Wv;
    const float* bias = (mat == 0) ? bq : (mat == 1) ? bk : bv;
    const float* wvp  = (mat == 0) ? qw : kw;

    const int rowbase = (mat == 2) ? (blk - 256) * 64 : (blk & 127) * 128;

    for (int wdx = tid; wdx < 2048; wdx += 128) {
        const int j = wdx >> 5, p = wdx & 31;
        float2 w2 = *(const float2*)(W + j*64 + 2*p);
        const int pos = j*34 + ((p & 24) | (((p & 3) << 1) | ((p >> 2) & 1)));
        if (mat < 2) {
            sWbh[pos] = pack2f(w2);
        } else {
            __nv_bfloat16 h0 = __float2bfloat16(w2.x), h1 = __float2bfloat16(w2.y);
            sWbh[pos] = ((uint32_t)__bfloat16_as_ushort(h1) << 16) |
                        (uint32_t)__bfloat16_as_ushort(h0);
            sWbl[pos] = pack2(w2.x - __bfloat162float(h0), w2.y - __bfloat162float(h1));
        }
    }
    if (tid < 64) {
        if (mat < 2) {
            float m = wvp[tid] * (1.0f/64.0f);
            sCo[tid] = m; sCo[64 + tid] = bias[tid] * m;
        } else {
            sCo[tid] = bias[tid];
        }
    }

    if (mat < 2) {
        const int rb = wr * 32;
        uint32_t A[2][4][4];
        #pragma unroll
        for (int rt = 0; rt < 2; rt++) {
            const float* xg = src + (size_t)(rowbase + rb + rt*16 + g)*64 + 2*tg;
            const float* xh = xg + 8*64;
            #pragma unroll
            for (int ks = 0; ks < 4; ks++) {
                float2 x0 = *(const float2*)(xg + ks*16);
                float2 x1 = *(const float2*)(xh + ks*16);
                float2 x2 = *(const float2*)(xg + ks*16 + 8);
                float2 x3 = *(const float2*)(xh + ks*16 + 8);
                A[rt][ks][0] = pack2f(x0); A[rt][ks][1] = pack2f(x1);
                A[rt][ks][2] = pack2f(x2); A[rt][ks][3] = pack2f(x3);
            }
        }
        __syncthreads();
        #pragma unroll
        for (int rt = 0; rt < 2; rt++) {
            const int r0 = rb + rt*16 + g;
            #pragma unroll
            for (int j8 = 0; j8 < 8; j8++) {
                const uint32_t* wrow = sWbh + (j8*8 + g)*34 + 2*tg;
                float C[4] = {0.f, 0.f, 0.f, 0.f};
                #pragma unroll
                for (int ks = 0; ks < 4; ks++) {
                    uint2 bf = *(const uint2*)(wrow + ks*8);
                    mma_bf16(C, A[rt][ks], bf.x, bf.y);
                }
                const int c = j8*8 + 2*tg;
                const float m0 = sCo[c], m1 = sCo[c+1];
                const float a0 = sCo[64+c], a1 = sCo[64+c+1];
                const int wp = permw(j8*4 + tg);
                sQ[(r0    )*36 + wp] = pack2(fmaf(C[0],m0,a0), fmaf(C[1],m1,a1));
                sQ[(r0 + 8)*36 + wp] = pack2(fmaf(C[2],m0,a0), fmaf(C[3],m1,a1));
            }
        }
        __syncthreads();
        uint32_t* dst = ((mat == 0) ? g_qb : g_kb) + (size_t)rowbase * 32;
        #pragma unroll
        for (int i = 0; i < 8; i++) {
            const int c = tid + i*128;
            const int row = c >> 3, qq = c & 7;
            uint4 u = *(const uint4*)(sQ + row*36 + 4*qq);
            *((uint4*)dst + (size_t)row*8 + qq) = u;
        }
    } else {
        const int r0 = wr*16 + g;
        uint32_t Ah[4][4], Al[4][4];
        {
            const float* xg = src + (size_t)(rowbase + r0)*64 + 2*tg;
            const float* xh = xg + 8*64;
            #pragma unroll
            for (int ks = 0; ks < 4; ks++) {
                float2 xs[4];
                xs[0] = *(const float2*)(xg + ks*16);
                xs[1] = *(const float2*)(xh + ks*16);
                xs[2] = *(const float2*)(xg + ks*16 + 8);
                xs[3] = *(const float2*)(xh + ks*16 + 8);
                #pragma unroll
                for (int e = 0; e < 4; e++) {
                    __nv_bfloat16 h0 = __float2bfloat16(xs[e].x);
                    __nv_bfloat16 h1 = __float2bfloat16(xs[e].y);
                    Ah[ks][e] = ((uint32_t)__bfloat16_as_ushort(h1) << 16) |
                                (uint32_t)__bfloat16_as_ushort(h0);
                    Al[ks][e] = pack2(xs[e].x - __bfloat162float(h0),
                                      xs[e].y - __bfloat162float(h1));
                }
            }
        }
        __syncthreads();
        #pragma unroll
        for (int j8 = 0; j8 < 8; j8++) {
            const uint32_t* wrh = sWbh + (j8*8 + g)*34 + 2*tg;
            const uint32_t* wrl = sWbl + (j8*8 + g)*34 + 2*tg;
            float C[4] = {0.f, 0.f, 0.f, 0.f};
            #pragma unroll
            for (int ks = 0; ks < 4; ks++) {
                uint2 bh = *(const uint2*)(wrh + ks*8);
                uint2 bl = *(const uint2*)(wrl + ks*8);
                mma_bf16(C, Ah[ks], bh.x, bh.y);
                mma_bf16(C, Al[ks], bh.x, bh.y);
                mma_bf16(C, Ah[ks], bl.x, bl.y);
            }
            const int d = j8*8 + 2*tg;
            const float a0 = sCo[d], a1 = sCo[d+1];
            *(float2*)(sVt + (r0    )*66 + d) = make_float2(C[0]+a0, C[1]+a1);
            *(float2*)(sVt + (r0 + 8)*66 + d) = make_float2(C[2]+a0, C[3]+a1);
        }
        __syncthreads();
        {
            const int d  = tid >> 1;
            const int sh = tid & 1;
            const int b  = rowbase >> 12, sb = rowbase & (NS-1);
            uint32_t* dst = (uint32_t*)g_vh + (((size_t)(b*64 + d))*NS + sb)/2;
            #pragma unroll
            for (int j = 0; j < 2; j++) {
                const int sblk = sh*2 + j;
                float x[16];
                #pragma unroll
                for (int i = 0; i < 16; i++) x[i] = sVt[(sblk*16 + i)*66 + d];
                uint4* o4 = (uint4*)(dst + sblk*8);
                o4[0] = make_uint4(pack2(x[0],x[1]), pack2(x[ 8],x[ 9]),
                                   pack2(x[2],x[3]), pack2(x[10],x[11]));
                o4[1] = make_uint4(pack2(x[4],x[5]), pack2(x[12],x[13]),
                                   pack2(x[6],x[7]), pack2(x[14],x[15]));
            }
        }
        {
            const int d    = tid & 63;
            const int half = tid >> 6;
            float acc = 0.0f;
            #pragma unroll
            for (int i = 0; i < 32; i++)
                acc += sVt[(half*32 + i)*66 + d];
            sPart[tid] = acc;
        }
        __syncthreads();
        if (tid < 64)
            g_svp[(size_t)(blk - 256)*64 + tid] = sPart[tid] + sPart[tid + 64];
    }
}

// ===========================================================================
// Reduce V column-sum partials (deterministic fixed order).
// ===========================================================================
__global__ __launch_bounds__(64) void sumv_kernel()
{
    const int b = blockIdx.x;
    const int d = threadIdx.x;
    float acc = 0.0f;
    #pragma unroll 8
    for (int j = 0; j < 64; j++)
        acc += g_svp[(size_t)(b*64 + j)*64 + d];
    g_sv[b*64 + d] = acc;
}

// ===========================================================================
// Flash attention (R14 structure), SPLIT-K over key halves (blockIdx.z):
// each CTA processes 2048 keys and writes fp32 partials (O_p, l_p).
//   O = (SumV + Sum_z O_z) / (4096 + Sum_z l_z)   [combine kernel]
// ===========================================================================
#define PQK 40
#define PV  40
#define KWORDS (KT*PQK)
#define VWORDS (64*PV)
#define STG (KWORDS + VWORDS)

#define POLY_E(sv) ((sv) * fmaf((sv), fmaf((sv), 0.16666667f, 0.5f), 1.0f))

__global__ __launch_bounds__(256, 2) void attn_kernel()
{
    __shared__ __align__(16) uint32_t buf[2*STG];
    float* buff = (float*)buf;

    const int tid  = threadIdx.x;
    const int lane = tid & 31;
    const int w    = tid >> 5;
    const int wr   = w & 3;
    const int hf   = w >> 2;
    const int g    = lane >> 2;
    const int tg   = lane & 3;
    const int b    = blockIdx.y;
    const int z    = blockIdx.z;
    const int kt0  = z * HT;
    const int qbase = blockIdx.x * QT;
    const uint32_t sbase = smem_to_u32(buf);

    {
        const int qr   = tid >> 1;
        const int half = tid & 1;
        const uint4* qg = (const uint4*)g_qb + ((size_t)(b*NS + qbase + qr)) * 8;
        #pragma unroll
        for (int j = 0; j < 4; j++)
            *(uint4*)(buf + qr*PQK + (half*4 + j)*4) = qg[half*4 + j];
    }
    __syncthreads();

    uint32_t qa[2][4][4];
    #pragma unroll
    for (int rt = 0; rt < 2; rt++) {
        const int r0 = wr*32 + rt*16 + g;
        #pragma unroll
        for (int kp = 0; kp < 4; kp++) {
            uint2 u0 = *(const uint2*)(buf + (r0  )*PQK + kp*8 + 2*tg);
            uint2 u1 = *(const uint2*)(buf + (r0+8)*PQK + kp*8 + 2*tg);
            qa[rt][kp][0] = u0.x; qa[rt][kp][1] = u1.x;
            qa[rt][kp][2] = u0.y; qa[rt][kp][3] = u1.y;
        }
    }
    __syncthreads();

    const int kr0  = tid >> 3;
    const int slot = tid & 7;
    const uint4* kgm  = (const uint4*)g_kb + (size_t)b*NS*8;
    const uint4* vhg0 = (const uint4*)g_vh + ((size_t)(b*64 + kr0     ))*(NS/8);
    const uint4* vhg1 = (const uint4*)g_vh + ((size_t)(b*64 + kr0 + 32))*(NS/8);
    const uint32_t kst0 = sbase + ((kr0     )*PQK + slot*4)*4;
    const uint32_t kst1 = sbase + ((kr0 + 32)*PQK + slot*4)*4;
    const uint32_t vst0 = sbase + (KWORDS + (kr0     )*PV + slot*4)*4;
    const uint32_t vst1 = sbase + (KWORDS + (kr0 + 32)*PV + slot*4)*4;

    {
        cpa16(kst0, kgm + (size_t)(kt0*KT + kr0     )*8 + slot);
        cpa16(kst1, kgm + (size_t)(kt0*KT + kr0 + 32)*8 + slot);
        cpa16(vst0, vhg0 + kt0*8 + slot);
        cpa16(vst1, vhg1 + kt0*8 + slot);
        CP_COMMIT();
    }

    float o[2][8][4];
    #pragma unroll
    for (int rt = 0; rt < 2; rt++)
        #pragma unroll
        for (int n = 0; n < 8; n++)
            #pragma unroll
            for (int e = 0; e < 4; e++) o[rt][n][e] = 0.0f;
    float lsum[2][2] = {{0.f,0.f},{0.f,0.f}};

    #pragma unroll 1
    for (int kt = kt0; kt < kt0 + HT; kt++) {
        const int cur = kt & 1;
        CP_WAIT0();
        __syncthreads();
        if (kt + 1 < kt0 + HT) {
            const uint32_t off = (cur^1) * (STG*4);
            cpa16(kst0 + off, kgm + (size_t)((kt+1)*KT + kr0     )*8 + slot);
            cpa16(kst1 + off, kgm + (size_t)((kt+1)*KT + kr0 + 32)*8 + slot);
            cpa16(vst0 + off, vhg0 + (kt+1)*8 + slot);
            cpa16(vst1 + off, vhg1 + (kt+1)*8 + slot);
            CP_COMMIT();
        }
        const uint32_t* sK = buf + cur*STG;
        const uint32_t* sV = sK + KWORDS;

        float s[2][4][4];
        #pragma unroll
        for (int n = 0; n < 4; n++) {
            const uint32_t* krow = sK + (hf*32 + n*8 + g)*PQK + 2*tg;
            uint2 k0 = *(const uint2*)(krow     );
            uint2 k1 = *(const uint2*)(krow +  8);
            uint2 k2 = *(const uint2*)(krow + 16);
            uint2 k3 = *(const uint2*)(krow + 24);
            float sa[2][4] = {{0.f,0.f,0.f,0.f},{0.f,0.f,0.f,0.f}};
            float sb[2][4] = {{0.f,0.f,0.f,0.f},{0.f,0.f,0.f,0.f}};
            mma_bf16(sa[0], qa[0][0], k0.x, k0.y);
            mma_bf16(sa[1], qa[1][0], k0.x, k0.y);
            mma_bf16(sb[0], qa[0][1], k1.x, k1.y);
            mma_bf16(sb[1], qa[1][1], k1.x, k1.y);
            mma_bf16(sa[0], qa[0][2], k2.x, k2.y);
            mma_bf16(sa[1], qa[1][2], k2.x, k2.y);
            mma_bf16(sb[0], qa[0][3], k3.x, k3.y);
            mma_bf16(sb[1], qa[1][3], k3.x, k3.y);
            #pragma unroll
            for (int rt = 0; rt < 2; rt++)
                #pragma unroll
                for (int e = 0; e < 4; e++) s[rt][n][e] = sa[rt][e] + sb[rt][e];
        }

        uint32_t ea[2][2][4];
        #pragma unroll
        for (int rt = 0; rt < 2; rt++) {
            float ev[4][4];
            #pragma unroll
            for (int n = 0; n < 4; n++) {
                ev[n][0] = POLY_E(s[rt][n][0]);
                ev[n][1] = POLY_E(s[rt][n][1]);
                ev[n][2] = POLY_E(s[rt][n][2]);
                ev[n][3] = POLY_E(s[rt][n][3]);
                lsum[rt][0] += ev[n][0] + ev[n][1];
                lsum[rt][1] += ev[n][2] + ev[n][3];
            }
            #pragma unroll
            for (int ks = 0; ks < 2; ks++) {
                ea[rt][ks][0] = pack2(ev[2*ks  ][0], ev[2*ks  ][1]);
                ea[rt][ks][1] = pack2(ev[2*ks  ][2], ev[2*ks  ][3]);
                ea[rt][ks][2] = pack2(ev[2*ks+1][0], ev[2*ks+1][1]);
                ea[rt][ks][3] = pack2(ev[2*ks+1][2], ev[2*ks+1][3]);
            }
        }

        #pragma unroll
        for (int n = 0; n < 8; n++) {
            const uint32_t* vrow = sV + (n*8 + g)*PV + hf*16 + 2*tg;
            uint2 b0 = *(const uint2*)(vrow);
            uint2 b1 = *(const uint2*)(vrow + 8);
            mma_bf16(o[0][n], ea[0][0], b0.x, b0.y);
            mma_bf16(o[1][n], ea[1][0], b0.x, b0.y);
            mma_bf16(o[0][n], ea[0][1], b1.x, b1.y);
            mma_bf16(o[1][n], ea[1][1], b1.x, b1.y);
        }
    }
    __syncthreads();

    // ---------------- epilogue: combine 2 key-halves within CTA, write
    //                  fp32 partials (no SumV / no normalize here) ----------
    #pragma unroll
    for (int rt = 0; rt < 2; rt++)
        #pragma unroll
        for (int h = 0; h < 2; h++) {
            lsum[rt][h] += __shfl_xor_sync(0xffffffffu, lsum[rt][h], 1);
            lsum[rt][h] += __shfl_xor_sync(0xffffffffu, lsum[rt][h], 2);
        }

    if (hf == 1) {
        #pragma unroll
        for (int rt = 0; rt < 2; rt++) {
            const int r0 = wr*32 + rt*16 + g;
            #pragma unroll
            for (int n = 0; n < 8; n++) {
                *(float2*)(buff + (size_t)r0*64 + n*8 + 2*tg)     = make_float2(o[rt][n][0], o[rt][n][1]);
                *(float2*)(buff + (size_t)(r0+8)*64 + n*8 + 2*tg) = make_float2(o[rt][n][2], o[rt][n][3]);
            }
            if (tg == 0) {
                buff[8192 + r0]     = lsum[rt][0];
                buff[8192 + r0 + 8] = lsum[rt][1];
            }
        }
    }
    __syncthreads();
    if (hf == 0) {
        float* op = g_op + ((size_t)z*NB + b)*NS*64 + (size_t)qbase*64;
        float* lp = g_lp + ((size_t)z*NB + b)*NS + qbase;
        #pragma unroll
        for (int rt = 0; rt < 2; rt++) {
            const int r0 = wr*32 + rt*16 + g;
            if (tg == 0) {
                lp[r0]     = lsum[rt][0] + buff[8192 + r0];
                lp[r0 + 8] = lsum[rt][1] + buff[8192 + r0 + 8];
            }
            #pragma unroll
            for (int n = 0; n < 8; n++) {
                float2 e0 = *(float2*)(buff + (size_t)r0*64 + n*8 + 2*tg);
                float2 e1 = *(float2*)(buff + (size_t)(r0+8)*64 + n*8 + 2*tg);
                *(float2*)(op + (size_t)r0*64 + n*8 + 2*tg) =
                    make_float2(o[rt][n][0] + e0.x, o[rt][n][1] + e0.y);
                *(float2*)(op + (size_t)(r0+8)*64 + n*8 + 2*tg) =
                    make_float2(o[rt][n][2] + e1.x, o[rt][n][3] + e1.y);
            }
        }
    }
}

// ===========================================================================
// Combine: out = (SumV + O0 + O1) / (4096 + l0 + l1). 256 x 256.
// ===========================================================================
__global__ __launch_bounds__(256) void combine_kernel(float* __restrict__ out)
{
    const int task = blockIdx.x*256 + threadIdx.x;   // 65536 tasks
    const int row  = task >> 2;                      // b*NS + s
    const int qd   = task & 3;                       // 16-float chunk
    const int b    = row >> 12;
    const float l0 = g_lp[row];
    const float l1 = g_lp[NB*NS + row];
    const float inv = 1.0f / (4096.0f + l0 + l1);
    const float4* o0 = (const float4*)(g_op + (size_t)row*64) + qd*4;
    const float4* o1 = (const float4*)(g_op + (size_t)NB*NS*64 + (size_t)row*64) + qd*4;
    const float4* sv = (const float4*)(g_sv + b*64) + qd*4;
    float4* dst = (float4*)(out + (size_t)row*64) + qd*4;
    #pragma unroll
    for (int i = 0; i < 4; i++) {
        float4 a = o0[i], c = o1[i], s = sv[i];
        dst[i] = make_float4((s.x + a.x + c.x)*inv, (s.y + a.y + c.y)*inv,
                             (s.z + a.z + c.z)*inv, (s.w + a.w + c.w)*inv);
    }
}

// ---------------------------------------------------------------------------
// Inputs: 0:q 1:k 2:v 3:attn_mask 4:Wq 5:bq 6:Wk 7:bk 8:Wv 9:bv 10:qw 11:kw
// attn_mask is a broadcast scalar added to all scores -> softmax-invariant.
// ---------------------------------------------------------------------------
extern "C" void kernel_launch(void* const* d_in, const int* in_sizes, int n_in,
                              void* d_out, int out_size)
{
    (void)in_sizes; (void)n_in; (void)out_size;
    proj_kernel<<<512, 128>>>(
        (const float*)d_in[0], (const float*)d_in[1], (const float*)d_in[2],
        (const float*)d_in[4], (const float*)d_in[5],
        (const float*)d_in[6], (const float*)d_in[7],
        (const float*)d_in[8], (const float*)d_in[9],
        (const float*)d_in[10], (const float*)d_in[11]);
    sumv_kernel<<<NB, 64>>>();
    attn_kernel<<<dim3(NS/QT, NB, 2), 256>>>();
    combine_kernel<<<256, 256>>>((float*)d_out);
}

// round 17
// speedup vs baseline: 1.1831x; 1.1684x over previous
#include <cuda_runtime.h>
#include <cuda_bf16.h>
#include <cstdint>

#define NB 4
#define NS 4096
#define QT 128              // q rows per CTA (attn)
#define KT 64               // keys per tile (attn)
#define NIT (NS/KT)         // 64 tiles

// Projected tensors, module-static scratch.
__device__ uint32_t      g_qb[(size_t)NB*NS*32];   // packed bf16 pairs, perm'd
__device__ uint32_t      g_kb[(size_t)NB*NS*32];
__device__ __nv_bfloat16 g_vh[(size_t)NB*64*NS];   // bf16 V [b][d][s], s perm'd
__device__ float         g_svp[256*64];            // per-V-block column-sum partials
__device__ float         g_sv[NB*64];              // exact fp32 column sums of V

__device__ __forceinline__ uint32_t smem_to_u32(const void* p) {
    uint32_t a;
    asm("{ .reg .u64 t; cvta.to.shared.u64 t, %1; cvt.u32.u64 %0, t; }" : "=r"(a) : "l"(p));
    return a;
}
__device__ __forceinline__ void cpa16(uint32_t dst, const void* src) {
    asm volatile("cp.async.cg.shared.global [%0], [%1], 16;" :: "r"(dst), "l"(src) : "memory");
}
#define CP_COMMIT() asm volatile("cp.async.commit_group;" ::: "memory")
#define CP_WAIT0()  asm volatile("cp.async.wait_group 0;" ::: "memory")

__device__ __forceinline__ void mma_bf16(float c[4], const uint32_t a[4],
                                         uint32_t b0, uint32_t b1) {
    asm volatile("mma.sync.aligned.m16n8k16.row.col.f32.bf16.bf16.f32 "
        "{%0,%1,%2,%3}, {%4,%5,%6,%7}, {%8,%9}, {%0,%1,%2,%3};"
        : "+f"(c[0]), "+f"(c[1]), "+f"(c[2]), "+f"(c[3])
        : "r"(a[0]), "r"(a[1]), "r"(a[2]), "r"(a[3]), "r"(b0), "r"(b1));
}
__device__ __forceinline__ uint32_t pack2(float lo, float hi) {
    __nv_bfloat162 h = __float22bfloat162_rn(make_float2(lo, hi));
    return *reinterpret_cast<uint32_t*>(&h);
}
__device__ __forceinline__ uint32_t pack2f(float2 v) { return pack2(v.x, v.y); }
// fragment word permutation within 8-word groups
__device__ __forceinline__ int permw(int w) {
    return (w & ~7) | (((w & 3) << 1) | ((w >> 2) & 1));
}

// ===========================================================================
// Projection via tensor cores, A-frags direct from gmem. Grid 768 x 128.
//   blocks [0,256)  : Q, 64 rows each
//   blocks [256,512): K, 64 rows each
//   blocks [512,768): V, 64 rows each (hi/lo split, 3 MMA chains)
// ===========================================================================
__global__ __launch_bounds__(128) void proj_kernel(
    const float* __restrict__ q, const float* __restrict__ k, const float* __restrict__ v,
    const float* __restrict__ Wq, const float* __restrict__ bq,
    const float* __restrict__ Wk, const float* __restrict__ bk,
    const float* __restrict__ Wv, const float* __restrict__ bv,
    const float* __restrict__ qw, const float* __restrict__ kw)
{
    __shared__ __align__(16) char smem[36864];
    uint32_t* sWbh = (uint32_t*)smem;
    uint32_t* sWbl = (uint32_t*)(smem + 8704);
    float*    sCo  = (float*)(smem + 17408);
    uint32_t* sQ   = (uint32_t*)(smem + 17920);   // QK: 64x36 words
    float*    sVt  = (float*)(smem + 17920);      // V : 64x66 fp32
    float*    sPart= (float*)(smem + 36352);

    const int blk = blockIdx.x;
    const int mat = (blk < 256) ? 0 : (blk < 512) ? 1 : 2;
    const int tid = threadIdx.x;
    const int wr  = tid >> 5;
    const int lane = tid & 31;
    const int g   = lane >> 2;
    const int tg  = lane & 3;

    const float* src  = (mat == 0) ? q  : (mat == 1) ? k  : v;
    const float* W    = (mat == 0) ? Wq : (mat == 1) ? Wk : Wv;
    const float* bias = (mat == 0) ? bq : (mat == 1) ? bk : bv;
    const float* wvp  = (mat == 0) ? qw : kw;

    const int rowbase = (blk & 255) * 64;

    // ---- stage W packed bf16 (+lo for V), perm'd word layout ----
    for (int wdx = tid; wdx < 2048; wdx += 128) {
        const int j = wdx >> 5, p = wdx & 31;
        float2 w2 = *(const float2*)(W + j*64 + 2*p);
        const int pos = j*34 + ((p & 24) | (((p & 3) << 1) | ((p >> 2) & 1)));
        if (mat < 2) {
            sWbh[pos] = pack2f(w2);
        } else {
            __nv_bfloat16 h0 = __float2bfloat16(w2.x), h1 = __float2bfloat16(w2.y);
            sWbh[pos] = ((uint32_t)__bfloat16_as_ushort(h1) << 16) |
                        (uint32_t)__bfloat16_as_ushort(h0);
            sWbl[pos] = pack2(w2.x - __bfloat162float(h0), w2.y - __bfloat162float(h1));
        }
    }
    if (tid < 64) {
        if (mat < 2) {
            float m = wvp[tid] * (1.0f/64.0f);
            sCo[tid] = m; sCo[64 + tid] = bias[tid] * m;
        } else {
            sCo[tid] = bias[tid];
        }
    }

    const int r0 = wr*16 + g;

    if (mat < 2) {
        // ---------------- Q/K path (64 rows, warp owns 16) ----------------
        uint32_t A[4][4];
        {
            const float* xg = src + (size_t)(rowbase + r0)*64 + 2*tg;
            const float* xh = xg + 8*64;
            #pragma unroll
            for (int ks = 0; ks < 4; ks++) {
                float2 x0 = *(const float2*)(xg + ks*16);
                float2 x1 = *(const float2*)(xh + ks*16);
                float2 x2 = *(const float2*)(xg + ks*16 + 8);
                float2 x3 = *(const float2*)(xh + ks*16 + 8);
                A[ks][0] = pack2f(x0); A[ks][1] = pack2f(x1);
                A[ks][2] = pack2f(x2); A[ks][3] = pack2f(x3);
            }
        }
        __syncthreads();
        #pragma unroll
        for (int j8 = 0; j8 < 8; j8++) {
            const uint32_t* wrow = sWbh + (j8*8 + g)*34 + 2*tg;
            float C[4] = {0.f, 0.f, 0.f, 0.f};
            #pragma unroll
            for (int ks = 0; ks < 4; ks++) {
                uint2 bf = *(const uint2*)(wrow + ks*8);
                mma_bf16(C, A[ks], bf.x, bf.y);
            }
            const int c = j8*8 + 2*tg;
            const float m0 = sCo[c], m1 = sCo[c+1];
            const float a0 = sCo[64+c], a1 = sCo[64+c+1];
            const int wp = permw(j8*4 + tg);
            sQ[(r0    )*36 + wp] = pack2(fmaf(C[0],m0,a0), fmaf(C[1],m1,a1));
            sQ[(r0 + 8)*36 + wp] = pack2(fmaf(C[2],m0,a0), fmaf(C[3],m1,a1));
        }
        __syncthreads();
        uint32_t* dst = ((mat == 0) ? g_qb : g_kb) + (size_t)rowbase * 32;
        #pragma unroll
        for (int i = 0; i < 4; i++) {
            const int c = tid + i*128;            // 512 uint4
            const int row = c >> 3, qq = c & 7;
            uint4 u = *(const uint4*)(sQ + row*36 + 4*qq);
            *((uint4*)dst + (size_t)row*8 + qq) = u;
        }
    } else {
        // ---------------- V path (hi/lo x hi/lo, 3 chains) ----------------
        uint32_t Ah[4][4], Al[4][4];
        {
            const float* xg = src + (size_t)(rowbase + r0)*64 + 2*tg;
            const float* xh = xg + 8*64;
            #pragma unroll
            for (int ks = 0; ks < 4; ks++) {
                float2 xs[4];
                xs[0] = *(const float2*)(xg + ks*16);
                xs[1] = *(const float2*)(xh + ks*16);
                xs[2] = *(const float2*)(xg + ks*16 + 8);
                xs[3] = *(const float2*)(xh + ks*16 + 8);
                #pragma unroll
                for (int e = 0; e < 4; e++) {
                    __nv_bfloat16 h0 = __float2bfloat16(xs[e].x);
                    __nv_bfloat16 h1 = __float2bfloat16(xs[e].y);
                    Ah[ks][e] = ((uint32_t)__bfloat16_as_ushort(h1) << 16) |
                                (uint32_t)__bfloat16_as_ushort(h0);
                    Al[ks][e] = pack2(xs[e].x - __bfloat162float(h0),
                                      xs[e].y - __bfloat162float(h1));
                }
            }
        }
        __syncthreads();
        #pragma unroll
        for (int j8 = 0; j8 < 8; j8++) {
            const uint32_t* wrh = sWbh + (j8*8 + g)*34 + 2*tg;
            const uint32_t* wrl = sWbl + (j8*8 + g)*34 + 2*tg;
            float C[4] = {0.f, 0.f, 0.f, 0.f};
            #pragma unroll
            for (int ks = 0; ks < 4; ks++) {
                uint2 bh = *(const uint2*)(wrh + ks*8);
                uint2 bl = *(const uint2*)(wrl + ks*8);
                mma_bf16(C, Ah[ks], bh.x, bh.y);
                mma_bf16(C, Al[ks], bh.x, bh.y);
                mma_bf16(C, Ah[ks], bl.x, bl.y);
            }
            const int d = j8*8 + 2*tg;
            const float a0 = sCo[d], a1 = sCo[d+1];
            *(float2*)(sVt + (r0    )*66 + d) = make_float2(C[0]+a0, C[1]+a1);
            *(float2*)(sVt + (r0 + 8)*66 + d) = make_float2(C[2]+a0, C[3]+a1);
        }
        __syncthreads();
        {
            const int d  = tid >> 1;
            const int sh = tid & 1;
            const int b  = rowbase >> 12, sb = rowbase & (NS-1);
            uint32_t* dst = (uint32_t*)g_vh + (((size_t)(b*64 + d))*NS + sb)/2;
            #pragma unroll
            for (int j = 0; j < 2; j++) {
                const int sblk = sh*2 + j;
                float x[16];
                #pragma unroll
                for (int i = 0; i < 16; i++) x[i] = sVt[(sblk*16 + i)*66 + d];
                uint4* o4 = (uint4*)(dst + sblk*8);
                o4[0] = make_uint4(pack2(x[0],x[1]), pack2(x[ 8],x[ 9]),
                                   pack2(x[2],x[3]), pack2(x[10],x[11]));
                o4[1] = make_uint4(pack2(x[4],x[5]), pack2(x[12],x[13]),
                                   pack2(x[6],x[7]), pack2(x[14],x[15]));
            }
        }
        {
            const int d    = tid & 63;
            const int half = tid >> 6;
            float acc = 0.0f;
            #pragma unroll
            for (int i = 0; i < 32; i++)
                acc += sVt[(half*32 + i)*66 + d];
            sPart[tid] = acc;
        }
        __syncthreads();
        if (tid < 64)
            g_svp[(size_t)(blk - 512)*64 + tid] = sPart[tid] + sPart[tid + 64];
    }
}

// ===========================================================================
// Reduce V column-sum partials (deterministic fixed order).
// ===========================================================================
__global__ __launch_bounds__(64) void sumv_kernel()
{
    const int b = blockIdx.x;
    const int d = threadIdx.x;
    float acc = 0.0f;
    #pragma unroll 8
    for (int j = 0; j < 64; j++)
        acc += g_svp[(size_t)(b*64 + j)*64 + d];
    g_sv[b*64 + d] = acc;
}

// ===========================================================================
// Flash attention (R14 structure) + V-fragment register prefetch:
//   O = (SumV + Sum e_i v_i) / (4096 + Sum e_i)
// ===========================================================================
#define PQK 40
#define PV  40
#define KWORDS (KT*PQK)
#define VWORDS (64*PV)
#define STG (KWORDS + VWORDS)

#define POLY_E(sv) ((sv) * fmaf((sv), fmaf((sv), 0.16666667f, 0.5f), 1.0f))

__global__ __launch_bounds__(256) void attn_kernel(float* __restrict__ out)
{
    __shared__ __align__(16) uint32_t buf[2*STG];
    float* buff = (float*)buf;

    const int tid  = threadIdx.x;
    const int lane = tid & 31;
    const int w    = tid >> 5;
    const int wr   = w & 3;
    const int hf   = w >> 2;
    const int g    = lane >> 2;
    const int tg   = lane & 3;
    const int b    = blockIdx.y;
    const int qbase = blockIdx.x * QT;
    const uint32_t sbase = smem_to_u32(buf);

    {
        const int qr   = tid >> 1;
        const int half = tid & 1;
        const uint4* qg = (const uint4*)g_qb + ((size_t)(b*NS + qbase + qr)) * 8;
        #pragma unroll
        for (int j = 0; j < 4; j++)
            *(uint4*)(buf + qr*PQK + (half*4 + j)*4) = qg[half*4 + j];
    }
    __syncthreads();

    uint32_t qa[2][4][4];
    #pragma unroll
    for (int rt = 0; rt < 2; rt++) {
        const int r0 = wr*32 + rt*16 + g;
        #pragma unroll
        for (int kp = 0; kp < 4; kp++) {
            uint2 u0 = *(const uint2*)(buf + (r0  )*PQK + kp*8 + 2*tg);
            uint2 u1 = *(const uint2*)(buf + (r0+8)*PQK + kp*8 + 2*tg);
            qa[rt][kp][0] = u0.x; qa[rt][kp][1] = u1.x;
            qa[rt][kp][2] = u0.y; qa[rt][kp][3] = u1.y;
        }
    }
    __syncthreads();

    const int kr0  = tid >> 3;
    const int slot = tid & 7;
    const uint4* kgm  = (const uint4*)g_kb + (size_t)b*NS*8;
    const uint4* vhg0 = (const uint4*)g_vh + ((size_t)(b*64 + kr0     ))*(NS/8);
    const uint4* vhg1 = (const uint4*)g_vh + ((size_t)(b*64 + kr0 + 32))*(NS/8);
    const uint32_t kst0 = sbase + ((kr0     )*PQK + slot*4)*4;
    const uint32_t kst1 = sbase + ((kr0 + 32)*PQK + slot*4)*4;
    const uint32_t vst0 = sbase + (KWORDS + (kr0     )*PV + slot*4)*4;
    const uint32_t vst1 = sbase + (KWORDS + (kr0 + 32)*PV + slot*4)*4;

    {
        cpa16(kst0, kgm + (size_t)(kr0     )*8 + slot);
        cpa16(kst1, kgm + (size_t)(kr0 + 32)*8 + slot);
        cpa16(vst0, vhg0 + slot);
        cpa16(vst1, vhg1 + slot);
        CP_COMMIT();
    }

    float o[2][8][4];
    #pragma unroll
    for (int rt = 0; rt < 2; rt++)
        #pragma unroll
        for (int n = 0; n < 8; n++)
            #pragma unroll
            for (int e = 0; e < 4; e++) o[rt][n][e] = 0.0f;
    float lsum[2][2] = {{0.f,0.f},{0.f,0.f}};

    #pragma unroll 1
    for (int kt = 0; kt < NIT; kt++) {
        const int cur = kt & 1;
        CP_WAIT0();
        __syncthreads();
        if (kt + 1 < NIT) {
            const uint32_t off = (cur^1) * (STG*4);
            cpa16(kst0 + off, kgm + (size_t)((kt+1)*KT + kr0     )*8 + slot);
            cpa16(kst1 + off, kgm + (size_t)((kt+1)*KT + kr0 + 32)*8 + slot);
            cpa16(vst0 + off, vhg0 + (kt+1)*8 + slot);
            cpa16(vst1 + off, vhg1 + (kt+1)*8 + slot);
            CP_COMMIT();
        }
        const uint32_t* sK = buf + cur*STG;
        const uint32_t* sV = sK + KWORDS;

        // ---- V-fragment register prefetch (consumed in MMA2, issued now so
        //      the 29-cyc LDS latency hides under MMA1) ----
        uint2 vf0[8], vf1[8];
        #pragma unroll
        for (int n = 0; n < 8; n++) {
            const uint32_t* vrow = sV + (n*8 + g)*PV + hf*16 + 2*tg;
            vf0[n] = *(const uint2*)(vrow);
            vf1[n] = *(const uint2*)(vrow + 8);
        }

        // ---- MMA1: S(32x32) = Q @ K_half^T ----
        float s[2][4][4];
        #pragma unroll
        for (int n = 0; n < 4; n++) {
            const uint32_t* krow = sK + (hf*32 + n*8 + g)*PQK + 2*tg;
            uint2 k0 = *(const uint2*)(krow     );
            uint2 k1 = *(const uint2*)(krow +  8);
            uint2 k2 = *(const uint2*)(krow + 16);
            uint2 k3 = *(const uint2*)(krow + 24);
            float sa[2][4] = {{0.f,0.f,0.f,0.f},{0.f,0.f,0.f,0.f}};
            float sb[2][4] = {{0.f,0.f,0.f,0.f},{0.f,0.f,0.f,0.f}};
            mma_bf16(sa[0], qa[0][0], k0.x, k0.y);
            mma_bf16(sa[1], qa[1][0], k0.x, k0.y);
            mma_bf16(sb[0], qa[0][1], k1.x, k1.y);
            mma_bf16(sb[1], qa[1][1], k1.x, k1.y);
            mma_bf16(sa[0], qa[0][2], k2.x, k2.y);
            mma_bf16(sa[1], qa[1][2], k2.x, k2.y);
            mma_bf16(sb[0], qa[0][3], k3.x, k3.y);
            mma_bf16(sb[1], qa[1][3], k3.x, k3.y);
            #pragma unroll
            for (int rt = 0; rt < 2; rt++)
                #pragma unroll
                for (int e = 0; e < 4; e++) s[rt][n][e] = sa[rt][e] + sb[rt][e];
        }

        // ---- e = poly(s); pack A-frags ----
        uint32_t ea[2][2][4];
        #pragma unroll
        for (int rt = 0; rt < 2; rt++) {
            float ev[4][4];
            #pragma unroll
            for (int n = 0; n < 4; n++) {
                ev[n][0] = POLY_E(s[rt][n][0]);
                ev[n][1] = POLY_E(s[rt][n][1]);
                ev[n][2] = POLY_E(s[rt][n][2]);
                ev[n][3] = POLY_E(s[rt][n][3]);
                lsum[rt][0] += ev[n][0] + ev[n][1];
                lsum[rt][1] += ev[n][2] + ev[n][3];
            }
            #pragma unroll
            for (int ks = 0; ks < 2; ks++) {
                ea[rt][ks][0] = pack2(ev[2*ks  ][0], ev[2*ks  ][1]);
                ea[rt][ks][1] = pack2(ev[2*ks  ][2], ev[2*ks  ][3]);
                ea[rt][ks][2] = pack2(ev[2*ks+1][0], ev[2*ks+1][1]);
                ea[rt][ks][3] = pack2(ev[2*ks+1][2], ev[2*ks+1][3]);
            }
        }

        // ---- MMA2: O(32x64) += E(32x32) @ Vh(32x64) (regs only) ----
        #pragma unroll
        for (int n = 0; n < 8; n++) {
            mma_bf16(o[0][n], ea[0][0], vf0[n].x, vf0[n].y);
            mma_bf16(o[1][n], ea[1][0], vf0[n].x, vf0[n].y);
            mma_bf16(o[0][n], ea[0][1], vf1[n].x, vf1[n].y);
            mma_bf16(o[1][n], ea[1][1], vf1[n].x, vf1[n].y);
        }
    }
    __syncthreads();

    // ---------------- epilogue: combine halves, add SumV, normalize --------
    #pragma unroll
    for (int rt = 0; rt < 2; rt++)
        #pragma unroll
        for (int h = 0; h < 2; h++) {
            lsum[rt][h] += __shfl_xor_sync(0xffffffffu, lsum[rt][h], 1);
            lsum[rt][h] += __shfl_xor_sync(0xffffffffu, lsum[rt][h], 2);
        }

    if (hf == 1) {
        #pragma unroll
        for (int rt = 0; rt < 2; rt++) {
            const int r0 = wr*32 + rt*16 + g;
            #pragma unroll
            for (int n = 0; n < 8; n++) {
                *(float2*)(buff + (size_t)r0*64 + n*8 + 2*tg)     = make_float2(o[rt][n][0], o[rt][n][1]);
                *(float2*)(buff + (size_t)(r0+8)*64 + n*8 + 2*tg) = make_float2(o[rt][n][2], o[rt][n][3]);
            }
            if (tg == 0) {
                buff[8192 + r0]     = lsum[rt][0];
                buff[8192 + r0 + 8] = lsum[rt][1];
            }
        }
    }
    __syncthreads();
    if (hf == 0) {
        float2 sv2[8];
        #pragma unroll
        for (int n = 0; n < 8; n++)
            sv2[n] = *(const float2*)(g_sv + b*64 + n*8 + 2*tg);
        #pragma unroll
        for (int rt = 0; rt < 2; rt++) {
            const int r0 = wr*32 + rt*16 + g;
            const float l0 = 1.0f / (4096.0f + lsum[rt][0] + buff[8192 + r0]);
            const float l1 = 1.0f / (4096.0f + lsum[rt][1] + buff[8192 + r0 + 8]);
            #pragma unroll
            for (int n = 0; n < 8; n++) {
                float2 e0 = *(float2*)(buff + (size_t)r0*64 + n*8 + 2*tg);
                float2 e1 = *(float2*)(buff + (size_t)(r0+8)*64 + n*8 + 2*tg);
                float2 v0 = make_float2((sv2[n].x + o[rt][n][0] + e0.x)*l0,
                                        (sv2[n].y + o[rt][n][1] + e0.y)*l0);
                float2 v1 = make_float2((sv2[n].x + o[rt][n][2] + e1.x)*l1,
                                        (sv2[n].y + o[rt][n][3] + e1.y)*l1);
                *(float2*)(out + ((size_t)(b*NS + qbase + r0    ))*64 + n*8 + 2*tg) = v0;
                *(float2*)(out + ((size_t)(b*NS + qbase + r0 + 8))*64 + n*8 + 2*tg) = v1;
            }
        }
    }
}

// ---------------------------------------------------------------------------
// Inputs: 0:q 1:k 2:v 3:attn_mask 4:Wq 5:bq 6:Wk 7:bk 8:Wv 9:bv 10:qw 11:kw
// attn_mask is a broadcast scalar added to all scores -> softmax-invariant.
// ---------------------------------------------------------------------------
extern "C" void kernel_launch(void* const* d_in, const int* in_sizes, int n_in,
                              void* d_out, int out_size)
{
    (void)in_sizes; (void)n_in; (void)out_size;
    proj_kernel<<<768, 128>>>(
        (const float*)d_in[0], (const float*)d_in[1], (const float*)d_in[2],
        (const float*)d_in[4], (const float*)d_in[5],
        (const float*)d_in[6], (const float*)d_in[7],
        (const float*)d_in[8], (const float*)d_in[9],
        (const float*)d_in[10], (const float*)d_in[11]);
    sumv_kernel<<<NB, 64>>>();
    attn_kernel<<<dim3(NS/QT, NB), 256>>>((float*)d_out);
}